// round 15
// baseline (speedup 1.0000x reference)
#include <cuda_runtime.h>

// ---------------------------------------------------------------------------
// Compile-time filter construction (double precision, folded to fp32 imms)
// ---------------------------------------------------------------------------
__host__ __device__ constexpr double d_abs(double x){ return x < 0 ? -x : x; }
__host__ __device__ constexpr double cexp_pos(double x){ double t=1.0,s=1.0; for(int n=1;n<60;n++){ t*=x/n; s+=t; } return s; }
__host__ __device__ constexpr double cexp(double x){ return x < 0.0 ? 1.0/cexp_pos(-x) : cexp_pos(x); }
__host__ __device__ constexpr double ccos(double x){ double x2=x*x,t=1.0,s=1.0; for(int n=1;n<30;n++){ t*=-x2/((2.0*n-1.0)*(2.0*n)); s+=t; } return s; }

struct K7 { float w[7][7]; };

__host__ __device__ constexpr K7 make_log(int r, double sigma){
    double tmp[7][7] = {}; double s = 0.0;
    for(int i=-r;i<=r;i++) for(int j=-r;j<=r;j++){
        double r2 = (double)(i*i + j*j);
        double g  = cexp(-r2/(2.0*sigma*sigma));
        double f  = (1.0 - r2/(2.0*sigma*sigma))*g;
        tmp[i+3][j+3] = -f;
        s += d_abs(f);
    }
    K7 k{};
    for(int i=0;i<7;i++) for(int j=0;j<7;j++) k.w[i][j] = (float)(tmp[i][j]/s);
    return k;
}

__host__ __device__ constexpr K7 make_gabor(double c, double sn){
    double tmp[7][7] = {}; double s = 0.0;
    for(int i=0;i<7;i++) for(int j=0;j<7;j++){
        double x = (double)(j-3), y = (double)(i-3);
        double xt = x*c + y*sn;
        double g = cexp(-(x*x + y*y)/8.0) * ccos(2.0*3.14159265358979323846*0.1*xt);
        tmp[i][j] = g; s += d_abs(g);
    }
    K7 k{};
    for(int i=0;i<7;i++) for(int j=0;j<7;j++) k.w[i][j] = (float)(tmp[i][j]/s);
    return k;
}

__host__ __device__ constexpr K7 make_lpf(){
    K7 k{};
    double b[3] = {0.25, 0.5, 0.25};
    for(int i=0;i<3;i++) for(int j=0;j<3;j++) k.w[i+2][j+2] = (float)(b[i]*b[j]);
    return k;
}

__host__ __device__ constexpr K7 make_hpf3(){
    K7 k{};
    for(int i=2;i<=4;i++) for(int j=2;j<=4;j++) k.w[i][j] = -1.0f;
    k.w[3][3] = 8.0f;
    return k;
}
__host__ __device__ constexpr K7 make_hpf5(){
    K7 k{};
    for(int i=1;i<=5;i++) for(int j=1;j<=5;j++) k.w[i][j] = -1.0f;
    k.w[3][3] = 24.0f;
    return k;
}

__host__ __device__ constexpr K7 make_even(const K7& a){
    K7 k{};
    for(int i=0;i<7;i++) for(int j=0;j<7;j++) k.w[i][j] = (a.w[i][j] + a.w[i][6-j]) * 0.5f;
    return k;
}
__host__ __device__ constexpr K7 make_odd(const K7& a){
    K7 k{};
    for(int i=0;i<7;i++) for(int j=0;j<7;j++) k.w[i][j] = (a.w[i][j] - a.w[i][6-j]) * 0.5f;
    return k;
}

__device__ constexpr double RS2 = 0.70710678118654752440;
__device__ constexpr K7 KL3   = make_log(1, 0.8);
__device__ constexpr K7 KL5   = make_log(2, 1.0);
__device__ constexpr K7 KL7   = make_log(3, 1.4);
__device__ constexpr K7 KG0   = make_gabor( 1.0, 0.0);
__device__ constexpr K7 KG45  = make_gabor( RS2, RS2);
__device__ constexpr K7 KG90  = make_gabor( 0.0, 1.0);
__device__ constexpr K7 KGE   = make_even(KG45);
__device__ constexpr K7 KGO   = make_odd(KG45);
__device__ constexpr K7 KLP   = make_lpf();
__device__ constexpr K7 KH3   = make_hpf3();
__device__ constexpr K7 KH5   = make_hpf5();

// ---------------------------------------------------------------------------
#define IMG_SZ 262144        // 512*512
#define PLANE  12582912      // 48*512*512
#define PITCH  72
#define BROWS  128           // circular buffer rows (&127)

__device__ __forceinline__ float addi(float a, float b){
    float d; asm("fma.rn.f32 %0, %1, 0f3F800000, %2;" : "=f"(d) : "f"(a), "f"(b)); return d;
}
__device__ __forceinline__ float subi(float a, float b){   // a - b
    float d; asm("fma.rn.f32 %0, %1, 0fBF800000, %2;" : "=f"(d) : "f"(b), "f"(a)); return d;
}

__device__ __forceinline__ float tanh01(float z){    // tanh(0.1*z) via MUFU.TANH
    float t;
    asm("tanh.approx.f32 %0, %1;" : "=f"(t) : "f"(z * 0.1f));
    return t;
}

__device__ __forceinline__ void cpasync4(unsigned int daddr, const float* src, unsigned int sz){
    asm volatile("cp.async.ca.shared.global [%0], [%1], 4, %2;"
                 :: "r"(daddr), "l"(src), "r"(sz) : "memory");
}

struct Acc { float l3,l5,l7,h3,h5,lp,g0,g90,gE,gO; };

// Even-symmetric taps for fold-level R. Processed in DESCENDING R order so
// the narrow-filter accumulators only come alive late (minimal peak pressure).
template<int R>
__device__ __forceinline__ void taps_even(float vs0, float hs1, float hs2, float hs3, Acc& p){
    p.l7  = fmaf(vs0, KL7.w[3+R][3], p.l7);
    p.l7  = fmaf(hs1, KL7.w[3+R][4], p.l7);
    p.l7  = fmaf(hs2, KL7.w[3+R][5], p.l7);
    p.l7  = fmaf(hs3, KL7.w[3+R][6], p.l7);
    p.g0  = fmaf(vs0, KG0.w[3+R][3], p.g0);
    p.g0  = fmaf(hs1, KG0.w[3+R][4], p.g0);
    p.g0  = fmaf(hs2, KG0.w[3+R][5], p.g0);
    p.g0  = fmaf(hs3, KG0.w[3+R][6], p.g0);
    p.g90 = fmaf(vs0, KG90.w[3+R][3], p.g90);
    p.g90 = fmaf(hs1, KG90.w[3+R][4], p.g90);
    p.g90 = fmaf(hs2, KG90.w[3+R][5], p.g90);
    p.g90 = fmaf(hs3, KG90.w[3+R][6], p.g90);
    p.gE  = fmaf(vs0, KGE.w[3+R][3], p.gE);
    p.gE  = fmaf(hs1, KGE.w[3+R][4], p.gE);
    p.gE  = fmaf(hs2, KGE.w[3+R][5], p.gE);
    p.gE  = fmaf(hs3, KGE.w[3+R][6], p.gE);
    if constexpr (R <= 2){
        p.l5 = fmaf(vs0, KL5.w[3+R][3], p.l5);
        p.l5 = fmaf(hs1, KL5.w[3+R][4], p.l5);
        p.l5 = fmaf(hs2, KL5.w[3+R][5], p.l5);
        p.h5 = fmaf(vs0, KH5.w[3+R][3], p.h5);
        p.h5 = fmaf(hs1, KH5.w[3+R][4], p.h5);
        p.h5 = fmaf(hs2, KH5.w[3+R][5], p.h5);
    }
    if constexpr (R <= 1){
        p.l3 = fmaf(vs0, KL3.w[3+R][3], p.l3);
        p.l3 = fmaf(hs1, KL3.w[3+R][4], p.l3);
        p.lp = fmaf(vs0, KLP.w[3+R][3], p.lp);
        p.lp = fmaf(hs1, KLP.w[3+R][4], p.lp);
        p.h3 = fmaf(vs0, KH3.w[3+R][3], p.h3);
        p.h3 = fmaf(hs1, KH3.w[3+R][4], p.h3);
    }
}

template<int R>
__device__ __forceinline__ void taps_odd(float hd1, float hd2, float hd3, Acc& p){
    p.gO = fmaf(hd1, KGO.w[3+R][4], p.gO);
    p.gO = fmaf(hd2, KGO.w[3+R][5], p.gO);
    p.gO = fmaf(hd3, KGO.w[3+R][6], p.gO);
}

__device__ __forceinline__ void load10(const float* p, float v[10]){
    float4 a = *(const float4*)p;
    float4 b = *(const float4*)(p + 4);
    float2 c = *(const float2*)(p + 8);
    v[0]=a.x; v[1]=a.y; v[2]=a.z; v[3]=a.w;
    v[4]=b.x; v[5]=b.y; v[6]=b.z; v[7]=b.w;
    v[8]=c.x; v[9]=c.y;
}

__device__ __forceinline__ void finalize(const Acc& p, float& lf, float& lo, float& ho, float& go){
    lf = p.lp;
    lo = fmaf(tanh01(fmaxf(fmaxf(p.l3, p.l5), p.l7)), 0.5f, 0.5f);
    ho = fmaf(tanh01(fmaxf(p.h3, p.h5)), 0.5f, 0.5f);
    go = tanh01(fmaxf(fmaxf(p.g0, p.g90), p.gE + fabsf(p.gO)));
}

// 32 output rows per iteration (each thread: rows ty and ty+16), halving the
// number of barrier/wait events vs 16-row iterations.
// Strips: blockIdx.y 0 -> 192 rows (6 iters), 1,2 -> 160 rows (5 iters).
// Grid = 8*3*48 = 1152 blocks.

__global__ __launch_bounds__(256, 4)
void msfilters_kernel(const float* __restrict__ x, float* __restrict__ out, int planes){
    __shared__ __align__(16) float sm[BROWS * PITCH];

    unsigned int smb;
    asm("{ .reg .u64 t; cvta.to.shared.u64 t, %1; cvt.u32.u64 %0, t; }"
        : "=r"(smb) : "l"((const void*)sm));

    const int img    = blockIdx.z;
    const int x0     = blockIdx.x * 64;
    const int ystart = (blockIdx.y == 0) ? 0 : (192 + (blockIdx.y - 1) * 160);
    const int iters  = (blockIdx.y == 0) ? 6 : 5;    // 192+160+160 = 512
    const float* src = x + (size_t)img * IMG_SZ;

    // initial fill: logical rows -3..34 -> phys rows 0..37 (first iteration
    // reads up to logical 34)
    for (int idx = threadIdx.x; idx < 38 * 70; idx += 256){
        int r = idx / 70;
        int c = idx - r * 70;
        int gy0 = ystart + r - 3;
        int gx0 = x0 + c - 3;
        float val = 0.0f;
        if ((unsigned)gy0 < 512u && (unsigned)gx0 < 512u) val = __ldg(src + gy0 * 512 + gx0);
        sm[r * PITCH + c] = val;
    }

    const int tx  = threadIdx.x & 15;
    const int ty  = threadIdx.x >> 4;
    const int tx4 = tx * 4;

    // prefetch: iteration k fills logical rows 35+32k .. 66+32k.
    // thread owns rows (35+32k+ty) and (51+32k+ty), cols tx+16j.
    int gy = ystart + 35 + ty;
    const float* srow = src + (size_t)gy * 512 + (x0 - 3 + tx);
    const int gxb = x0 - 3 + tx;
    const bool v0 = ((unsigned)gxb        < 512u);
    const bool v1 = ((unsigned)(gxb + 16) < 512u);
    const bool v2 = ((unsigned)(gxb + 32) < 512u);
    const bool v3 = ((unsigned)(gxb + 48) < 512u);
    const bool v4 = (tx < 6) && ((unsigned)(gxb + 64) < 512u);

    int ybase   = ty;            // phys top of read window for row-group 0
    int sts_row = 38 + ty;       // phys commit row for prefetch half 0

    float* outp = out + (size_t)img * IMG_SZ + (size_t)(ystart + ty) * 512 + x0 + tx4;

    __syncthreads();

#define PFHALF(STSROW, SPTR, GY) { \
        const bool gok = (GY) < 512; \
        unsigned int d0 = smb + (unsigned int)((((STSROW) & 127) * PITCH + tx) * 4); \
        cpasync4(d0,       (SPTR),      (v0 && gok) ? 4u : 0u); \
        cpasync4(d0 + 64,  (SPTR) + 16, (v1 && gok) ? 4u : 0u); \
        cpasync4(d0 + 128, (SPTR) + 32, (v2 && gok) ? 4u : 0u); \
        cpasync4(d0 + 192, (SPTR) + 48, (v3 && gok) ? 4u : 0u); \
        if (tx < 6) \
            cpasync4(d0 + 256, (SPTR) + 64, (v4 && gok) ? 4u : 0u); }

#define LEVEL(R, RP) { \
        float T[10], B[10]; \
        load10((RP)[3-R], T); \
        load10((RP)[3+R], B); \
        float V[10], W[10]; \
        _Pragma("unroll") \
        for (int c = 0; c < 10; c++){ V[c] = addi(T[c], B[c]); W[c] = subi(T[c], B[c]); } \
        _Pragma("unroll") \
        for (int p = 0; p < 4; p++){ \
            const int cc = p + 3; \
            float hs1 = addi(V[cc-1], V[cc+1]); \
            float hs2 = addi(V[cc-2], V[cc+2]); \
            float hs3 = addi(V[cc-3], V[cc+3]); \
            taps_even<R>(V[cc], hs1, hs2, hs3, acc[p]); \
            float hd1 = subi(W[cc-1], W[cc+1]); \
            float hd2 = subi(W[cc-2], W[cc+2]); \
            float hd3 = subi(W[cc-3], W[cc+3]); \
            taps_odd<R>(hd1, hd2, hd3, acc[p]); \
        } }

#define ROWGROUP(YB, OP) { \
        const float* rowp[7]; \
        _Pragma("unroll") \
        for (int d = 0; d < 7; d++) \
            rowp[d] = &sm[(((YB) + d) & 127) * PITCH + tx4]; \
        Acc acc[4] = {}; \
        LEVEL(3, rowp) \
        LEVEL(2, rowp) \
        LEVEL(1, rowp) \
        {   /* level 0 (center row) last; also emit the 'original' plane */ \
            float m[10]; load10(rowp[3], m); \
            float4 o4; o4.x = m[3]; o4.y = m[4]; o4.z = m[5]; o4.w = m[6]; \
            *(float4*)(OP) = o4; \
            _Pragma("unroll") \
            for (int p = 0; p < 4; p++){ \
                const int cc = p + 3; \
                float hs1 = addi(m[cc-1], m[cc+1]); \
                float hs2 = addi(m[cc-2], m[cc+2]); \
                float hs3 = addi(m[cc-3], m[cc+3]); \
                taps_even<0>(m[cc], hs1, hs2, hs3, acc[p]); \
            } \
        } \
        float4 lf4, lo4, ho4, go4; \
        finalize(acc[0], lf4.x, lo4.x, ho4.x, go4.x); \
        finalize(acc[1], lf4.y, lo4.y, ho4.y, go4.y); \
        finalize(acc[2], lf4.z, lo4.z, ho4.z, go4.z); \
        finalize(acc[3], lf4.w, lo4.w, ho4.w, go4.w); \
        *(float4*)((OP) + (size_t)PLANE)   = lf4; \
        *(float4*)((OP) + 2*(size_t)PLANE) = lo4; \
        *(float4*)((OP) + 3*(size_t)PLANE) = ho4; \
        if (planes >= 5) \
            *(float4*)((OP) + 4*(size_t)PLANE) = go4; }

    #pragma unroll 1
    for (int k = 0; k < iters; k++){
        // ---- async prefetch of next iteration's 32 rows into smem ----
        if (k < iters - 1){
            PFHALF(sts_row,      srow,            gy)
            PFHALF(sts_row + 16, srow + 16 * 512, gy + 16)
            asm volatile("cp.async.commit_group;" ::: "memory");
        }

        // ---- compute 32 output rows (two groups of 16) ----
        ROWGROUP(ybase,      outp)
        ROWGROUP(ybase + 16, outp + 16 * 512)

        // prefetch rows (phys 32k+38..32k+69) are disjoint (mod 128) from this
        // iteration's read window (phys 32k..32k+37): single barrier suffices.
        asm volatile("cp.async.wait_group 0;" ::: "memory");
        __syncthreads();

        gy      += 32;
        srow    += 32 * 512;
        outp    += 32 * 512;
        ybase   += 32;
        sts_row += 32;
    }
#undef ROWGROUP
#undef LEVEL
#undef PFHALF
}

extern "C" void kernel_launch(void* const* d_in, const int* in_sizes, int n_in,
                              void* d_out, int out_size){
    const float* x = (const float*)d_in[0];
    float* out = (float*)d_out;
    const int planes = out_size / PLANE;   // 5 when use_gabor
    dim3 grid(8, 3, 48);
    dim3 block(256);
    msfilters_kernel<<<grid, block>>>(x, out, planes);
}

// round 16
// speedup vs baseline: 1.0754x; 1.0754x over previous
#include <cuda_runtime.h>

// ---------------------------------------------------------------------------
// Compile-time filter construction (double precision, folded to fp32 imms)
// ---------------------------------------------------------------------------
__host__ __device__ constexpr double d_abs(double x){ return x < 0 ? -x : x; }
__host__ __device__ constexpr double cexp_pos(double x){ double t=1.0,s=1.0; for(int n=1;n<60;n++){ t*=x/n; s+=t; } return s; }
__host__ __device__ constexpr double cexp(double x){ return x < 0.0 ? 1.0/cexp_pos(-x) : cexp_pos(x); }
__host__ __device__ constexpr double ccos(double x){ double x2=x*x,t=1.0,s=1.0; for(int n=1;n<30;n++){ t*=-x2/((2.0*n-1.0)*(2.0*n)); s+=t; } return s; }

struct K7 { float w[7][7]; };

__host__ __device__ constexpr K7 make_log(int r, double sigma){
    double tmp[7][7] = {}; double s = 0.0;
    for(int i=-r;i<=r;i++) for(int j=-r;j<=r;j++){
        double r2 = (double)(i*i + j*j);
        double g  = cexp(-r2/(2.0*sigma*sigma));
        double f  = (1.0 - r2/(2.0*sigma*sigma))*g;
        tmp[i+3][j+3] = -f;
        s += d_abs(f);
    }
    K7 k{};
    for(int i=0;i<7;i++) for(int j=0;j<7;j++) k.w[i][j] = (float)(tmp[i][j]/s);
    return k;
}

__host__ __device__ constexpr K7 make_gabor(double c, double sn){
    double tmp[7][7] = {}; double s = 0.0;
    for(int i=0;i<7;i++) for(int j=0;j<7;j++){
        double x = (double)(j-3), y = (double)(i-3);
        double xt = x*c + y*sn;
        double g = cexp(-(x*x + y*y)/8.0) * ccos(2.0*3.14159265358979323846*0.1*xt);
        tmp[i][j] = g; s += d_abs(g);
    }
    K7 k{};
    for(int i=0;i<7;i++) for(int j=0;j<7;j++) k.w[i][j] = (float)(tmp[i][j]/s);
    return k;
}

__host__ __device__ constexpr K7 make_lpf(){
    K7 k{};
    double b[3] = {0.25, 0.5, 0.25};
    for(int i=0;i<3;i++) for(int j=0;j<3;j++) k.w[i+2][j+2] = (float)(b[i]*b[j]);
    return k;
}

__host__ __device__ constexpr K7 make_hpf3(){
    K7 k{};
    for(int i=2;i<=4;i++) for(int j=2;j<=4;j++) k.w[i][j] = -1.0f;
    k.w[3][3] = 8.0f;
    return k;
}
__host__ __device__ constexpr K7 make_hpf5(){
    K7 k{};
    for(int i=1;i<=5;i++) for(int j=1;j<=5;j++) k.w[i][j] = -1.0f;
    k.w[3][3] = 24.0f;
    return k;
}

__host__ __device__ constexpr K7 make_even(const K7& a){
    K7 k{};
    for(int i=0;i<7;i++) for(int j=0;j<7;j++) k.w[i][j] = (a.w[i][j] + a.w[i][6-j]) * 0.5f;
    return k;
}
__host__ __device__ constexpr K7 make_odd(const K7& a){
    K7 k{};
    for(int i=0;i<7;i++) for(int j=0;j<7;j++) k.w[i][j] = (a.w[i][j] - a.w[i][6-j]) * 0.5f;
    return k;
}

__device__ constexpr double RS2 = 0.70710678118654752440;
__device__ constexpr K7 KL3   = make_log(1, 0.8);
__device__ constexpr K7 KL5   = make_log(2, 1.0);
__device__ constexpr K7 KL7   = make_log(3, 1.4);
__device__ constexpr K7 KG0   = make_gabor( 1.0, 0.0);
__device__ constexpr K7 KG45  = make_gabor( RS2, RS2);
__device__ constexpr K7 KG90  = make_gabor( 0.0, 1.0);
__device__ constexpr K7 KGE   = make_even(KG45);
__device__ constexpr K7 KGO   = make_odd(KG45);
__device__ constexpr K7 KLP   = make_lpf();
__device__ constexpr K7 KH3   = make_hpf3();
__device__ constexpr K7 KH5   = make_hpf5();

// ---------------------------------------------------------------------------
#define IMG_SZ 262144        // 512*512
#define PLANE  12582912      // 48*512*512
#define PITCH  72
#define BROWS  64            // circular buffer rows (&63)

__device__ __forceinline__ float addi(float a, float b){
    float d; asm("fma.rn.f32 %0, %1, 0f3F800000, %2;" : "=f"(d) : "f"(a), "f"(b)); return d;
}
__device__ __forceinline__ float subi(float a, float b){   // a - b
    float d; asm("fma.rn.f32 %0, %1, 0fBF800000, %2;" : "=f"(d) : "f"(b), "f"(a)); return d;
}

__device__ __forceinline__ float tanh01(float z){    // tanh(0.1*z) via MUFU.TANH
    float t;
    asm("tanh.approx.f32 %0, %1;" : "=f"(t) : "f"(z * 0.1f));
    return t;
}

__device__ __forceinline__ void cpasync4(unsigned int daddr, const float* src, unsigned int sz){
    asm volatile("cp.async.ca.shared.global [%0], [%1], 4, %2;"
                 :: "r"(daddr), "l"(src), "r"(sz) : "memory");
}

// streaming (evict-first) 128-bit store: outputs are write-once, never re-read
__device__ __forceinline__ void stcs4(float* p, float4 v){
    asm volatile("st.global.cs.v4.f32 [%0], {%1, %2, %3, %4};"
                 :: "l"(p), "f"(v.x), "f"(v.y), "f"(v.z), "f"(v.w) : "memory");
}

struct Acc { float l3,l5,l7,h3,h5,lp,g0,g90,gE,gO; };

// Even-symmetric taps for fold-level R. Processed in DESCENDING R order so
// the narrow-filter accumulators (l3/lp/h3 at R<=1, l5/h5 at R<=2) only come
// alive late, minimizing peak register pressure during the wide levels.
template<int R>
__device__ __forceinline__ void taps_even(float vs0, float hs1, float hs2, float hs3, Acc& p){
    p.l7  = fmaf(vs0, KL7.w[3+R][3], p.l7);
    p.l7  = fmaf(hs1, KL7.w[3+R][4], p.l7);
    p.l7  = fmaf(hs2, KL7.w[3+R][5], p.l7);
    p.l7  = fmaf(hs3, KL7.w[3+R][6], p.l7);
    p.g0  = fmaf(vs0, KG0.w[3+R][3], p.g0);
    p.g0  = fmaf(hs1, KG0.w[3+R][4], p.g0);
    p.g0  = fmaf(hs2, KG0.w[3+R][5], p.g0);
    p.g0  = fmaf(hs3, KG0.w[3+R][6], p.g0);
    p.g90 = fmaf(vs0, KG90.w[3+R][3], p.g90);
    p.g90 = fmaf(hs1, KG90.w[3+R][4], p.g90);
    p.g90 = fmaf(hs2, KG90.w[3+R][5], p.g90);
    p.g90 = fmaf(hs3, KG90.w[3+R][6], p.g90);
    p.gE  = fmaf(vs0, KGE.w[3+R][3], p.gE);
    p.gE  = fmaf(hs1, KGE.w[3+R][4], p.gE);
    p.gE  = fmaf(hs2, KGE.w[3+R][5], p.gE);
    p.gE  = fmaf(hs3, KGE.w[3+R][6], p.gE);
    if constexpr (R <= 2){
        p.l5 = fmaf(vs0, KL5.w[3+R][3], p.l5);
        p.l5 = fmaf(hs1, KL5.w[3+R][4], p.l5);
        p.l5 = fmaf(hs2, KL5.w[3+R][5], p.l5);
        p.h5 = fmaf(vs0, KH5.w[3+R][3], p.h5);
        p.h5 = fmaf(hs1, KH5.w[3+R][4], p.h5);
        p.h5 = fmaf(hs2, KH5.w[3+R][5], p.h5);
    }
    if constexpr (R <= 1){
        p.l3 = fmaf(vs0, KL3.w[3+R][3], p.l3);
        p.l3 = fmaf(hs1, KL3.w[3+R][4], p.l3);
        p.lp = fmaf(vs0, KLP.w[3+R][3], p.lp);
        p.lp = fmaf(hs1, KLP.w[3+R][4], p.lp);
        p.h3 = fmaf(vs0, KH3.w[3+R][3], p.h3);
        p.h3 = fmaf(hs1, KH3.w[3+R][4], p.h3);
    }
}

template<int R>
__device__ __forceinline__ void taps_odd(float hd1, float hd2, float hd3, Acc& p){
    p.gO = fmaf(hd1, KGO.w[3+R][4], p.gO);
    p.gO = fmaf(hd2, KGO.w[3+R][5], p.gO);
    p.gO = fmaf(hd3, KGO.w[3+R][6], p.gO);
}

__device__ __forceinline__ void load10(const float* p, float v[10]){
    float4 a = *(const float4*)p;
    float4 b = *(const float4*)(p + 4);
    float2 c = *(const float2*)(p + 8);
    v[0]=a.x; v[1]=a.y; v[2]=a.z; v[3]=a.w;
    v[4]=b.x; v[5]=b.y; v[6]=b.z; v[7]=b.w;
    v[8]=c.x; v[9]=c.y;
}

__device__ __forceinline__ void finalize(const Acc& p, float& lf, float& lo, float& ho, float& go){
    lf = p.lp;
    lo = fmaf(tanh01(fmaxf(fmaxf(p.l3, p.l5), p.l7)), 0.5f, 0.5f);
    ho = fmaf(tanh01(fmaxf(p.h3, p.h5)), 0.5f, 0.5f);
    go = tanh01(fmaxf(fmaxf(p.g0, p.g90), p.gE + fabsf(p.gO)));
}

// Uneven y-strips: blockIdx.y 0,1 -> 176 rows (11 iters), blockIdx.y 2 -> 160
// rows (10 iters). Grid = 8*3*48 = 1152 blocks.
#define STRIP_H 176

__global__ __launch_bounds__(256, 4)
void msfilters_kernel(const float* __restrict__ x, float* __restrict__ out, int planes){
    __shared__ __align__(16) float sm[BROWS * PITCH];

    unsigned int smb;
    asm("{ .reg .u64 t; cvta.to.shared.u64 t, %1; cvt.u32.u64 %0, t; }"
        : "=r"(smb) : "l"((const void*)sm));

    const int img    = blockIdx.z;
    const int x0     = blockIdx.x * 64;
    const int ystart = blockIdx.y * STRIP_H;
    const int iters  = (blockIdx.y == 2) ? 10 : 11;   // 176+176+160 = 512
    const float* src = x + (size_t)img * IMG_SZ;

    // initial fill via cp.async (zero-fill OOB through size-0 trick):
    // logical rows -3..18 -> phys rows 0..21
    for (int idx = threadIdx.x; idx < 22 * 70; idx += 256){
        int r = idx / 70;
        int c = idx - r * 70;
        int gy0 = ystart + r - 3;
        int gx0 = x0 + c - 3;
        bool ok = ((unsigned)gy0 < 512u) && ((unsigned)gx0 < 512u);
        unsigned int d = smb + (unsigned int)((r * PITCH + c) * 4);
        cpasync4(d, src + gy0 * 512 + gx0, ok ? 4u : 0u);
    }
    asm volatile("cp.async.commit_group;" ::: "memory");

    const int tx  = threadIdx.x & 15;
    const int ty  = threadIdx.x >> 4;
    const int tx4 = tx * 4;

    // loop-invariant prefetch state: thread owns row ty, cols tx+16j of the halo
    int gy = ystart + 19 + ty;
    const float* srow = src + (size_t)gy * 512 + (x0 - 3 + tx);
    const int gxb = x0 - 3 + tx;
    const bool v0 = ((unsigned)gxb        < 512u);
    const bool v1 = ((unsigned)(gxb + 16) < 512u);
    const bool v2 = ((unsigned)(gxb + 32) < 512u);
    const bool v3 = ((unsigned)(gxb + 48) < 512u);
    const bool v4 = (tx < 6) && ((unsigned)(gxb + 64) < 512u);

    int ybase   = ty;            // (16k + ty) & 63
    int sts_row = 22 + ty;       // (22 + ty + 16k) & 63

    float* outp = out + (size_t)img * IMG_SZ + (size_t)(ystart + ty) * 512 + x0 + tx4;

    asm volatile("cp.async.wait_group 0;" ::: "memory");
    __syncthreads();

    #pragma unroll 1
    for (int k = 0; k < iters; k++){
        // ---- async prefetch of next 16 rows straight into smem ----
        if (k < iters - 1){
            const bool gok = gy < 512;
            unsigned int d0 = smb + (unsigned int)(((sts_row & 63) * PITCH + tx) * 4);
            cpasync4(d0,       srow,      (v0 && gok) ? 4u : 0u);
            cpasync4(d0 + 64,  srow + 16, (v1 && gok) ? 4u : 0u);
            cpasync4(d0 + 128, srow + 32, (v2 && gok) ? 4u : 0u);
            cpasync4(d0 + 192, srow + 48, (v3 && gok) ? 4u : 0u);
            if (tx < 6)
                cpasync4(d0 + 256, srow + 64, (v4 && gok) ? 4u : 0u);
            asm volatile("cp.async.commit_group;" ::: "memory");
        }

        // ---- compute current 16 output rows from circular smem window ----
        const float* rowp[7];
        #pragma unroll
        for (int d = 0; d < 7; d++)
            rowp[d] = &sm[((ybase + d) & 63) * PITCH + tx4];

        Acc acc[4] = {};

#define LEVEL(R) { \
        float T[10], B[10]; \
        load10(rowp[3-R], T); \
        load10(rowp[3+R], B); \
        float V[10], W[10]; \
        _Pragma("unroll") \
        for (int c = 0; c < 10; c++){ V[c] = addi(T[c], B[c]); W[c] = subi(T[c], B[c]); } \
        _Pragma("unroll") \
        for (int p = 0; p < 4; p++){ \
            const int cc = p + 3; \
            float hs1 = addi(V[cc-1], V[cc+1]); \
            float hs2 = addi(V[cc-2], V[cc+2]); \
            float hs3 = addi(V[cc-3], V[cc+3]); \
            taps_even<R>(V[cc], hs1, hs2, hs3, acc[p]); \
            float hd1 = subi(W[cc-1], W[cc+1]); \
            float hd2 = subi(W[cc-2], W[cc+2]); \
            float hd3 = subi(W[cc-3], W[cc+3]); \
            taps_odd<R>(hd1, hd2, hd3, acc[p]); \
        } }
        // Descending level order: wide filters first (5 accs live), narrow
        // accumulators materialize late -> minimal peak pressure, no spills.
        LEVEL(3)
        LEVEL(2)
        LEVEL(1)
#undef LEVEL

        {   // level 0 (center row) last; also emit the 'original' plane
            float m[10]; load10(rowp[3], m);
            float4 o4; o4.x = m[3]; o4.y = m[4]; o4.z = m[5]; o4.w = m[6];
            stcs4(outp, o4);
            #pragma unroll
            for (int p = 0; p < 4; p++){
                const int cc = p + 3;
                float hs1 = addi(m[cc-1], m[cc+1]);
                float hs2 = addi(m[cc-2], m[cc+2]);
                float hs3 = addi(m[cc-3], m[cc+3]);
                taps_even<0>(m[cc], hs1, hs2, hs3, acc[p]);
            }
        }

        float4 lf4, lo4, ho4, go4;
        finalize(acc[0], lf4.x, lo4.x, ho4.x, go4.x);
        finalize(acc[1], lf4.y, lo4.y, ho4.y, go4.y);
        finalize(acc[2], lf4.z, lo4.z, ho4.z, go4.z);
        finalize(acc[3], lf4.w, lo4.w, ho4.w, go4.w);

        stcs4(outp + (size_t)PLANE,   lf4);
        stcs4(outp + 2*(size_t)PLANE, lo4);
        stcs4(outp + 3*(size_t)PLANE, ho4);
        if (planes >= 5)
            stcs4(outp + 4*(size_t)PLANE, go4);

        // prefetch rows are disjoint (mod 64) from this iteration's read
        // window, so a single barrier per iteration suffices.
        asm volatile("cp.async.wait_group 0;" ::: "memory");
        __syncthreads();

        gy      += 16;
        srow    += 16 * 512;
        outp    += 16 * 512;
        ybase   += 16;
        sts_row += 16;
    }
}

extern "C" void kernel_launch(void* const* d_in, const int* in_sizes, int n_in,
                              void* d_out, int out_size){
    const float* x = (const float*)d_in[0];
    float* out = (float*)d_out;
    const int planes = out_size / PLANE;   // 5 when use_gabor
    dim3 grid(8, 3, 48);
    dim3 block(256);
    msfilters_kernel<<<grid, block>>>(x, out, planes);
}

// round 17
// speedup vs baseline: 1.0791x; 1.0034x over previous
#include <cuda_runtime.h>

// ---------------------------------------------------------------------------
// Compile-time filter construction (double precision, folded to fp32 imms)
// LoG / HPF / Gabor tables are pre-scaled by 0.1 (the pre-tanh scale):
// tanh(0.1*max(...)) == tanh(max(0.1*...)) since 0.1 > 0, and gE+|gO| is
// linear in the scale. LPF stays unscaled (raw output plane).
// ---------------------------------------------------------------------------
__host__ __device__ constexpr double d_abs(double x){ return x < 0 ? -x : x; }
__host__ __device__ constexpr double cexp_pos(double x){ double t=1.0,s=1.0; for(int n=1;n<60;n++){ t*=x/n; s+=t; } return s; }
__host__ __device__ constexpr double cexp(double x){ return x < 0.0 ? 1.0/cexp_pos(-x) : cexp_pos(x); }
__host__ __device__ constexpr double ccos(double x){ double x2=x*x,t=1.0,s=1.0; for(int n=1;n<30;n++){ t*=-x2/((2.0*n-1.0)*(2.0*n)); s+=t; } return s; }

struct K7 { float w[7][7]; };

__host__ __device__ constexpr K7 make_log(int r, double sigma){
    double tmp[7][7] = {}; double s = 0.0;
    for(int i=-r;i<=r;i++) for(int j=-r;j<=r;j++){
        double r2 = (double)(i*i + j*j);
        double g  = cexp(-r2/(2.0*sigma*sigma));
        double f  = (1.0 - r2/(2.0*sigma*sigma))*g;
        tmp[i+3][j+3] = -f;
        s += d_abs(f);
    }
    K7 k{};
    for(int i=0;i<7;i++) for(int j=0;j<7;j++) k.w[i][j] = (float)(0.1 * tmp[i][j]/s);
    return k;
}

__host__ __device__ constexpr K7 make_gabor(double c, double sn){
    double tmp[7][7] = {}; double s = 0.0;
    for(int i=0;i<7;i++) for(int j=0;j<7;j++){
        double x = (double)(j-3), y = (double)(i-3);
        double xt = x*c + y*sn;
        double g = cexp(-(x*x + y*y)/8.0) * ccos(2.0*3.14159265358979323846*0.1*xt);
        tmp[i][j] = g; s += d_abs(g);
    }
    K7 k{};
    for(int i=0;i<7;i++) for(int j=0;j<7;j++) k.w[i][j] = (float)(0.1 * tmp[i][j]/s);
    return k;
}

__host__ __device__ constexpr K7 make_lpf(){
    K7 k{};
    double b[3] = {0.25, 0.5, 0.25};
    for(int i=0;i<3;i++) for(int j=0;j<3;j++) k.w[i+2][j+2] = (float)(b[i]*b[j]);
    return k;
}

__host__ __device__ constexpr K7 make_hpf3(){
    K7 k{};
    for(int i=2;i<=4;i++) for(int j=2;j<=4;j++) k.w[i][j] = -0.1f;
    k.w[3][3] = 0.8f;
    return k;
}
__host__ __device__ constexpr K7 make_hpf5(){
    K7 k{};
    for(int i=1;i<=5;i++) for(int j=1;j<=5;j++) k.w[i][j] = -0.1f;
    k.w[3][3] = 2.4f;
    return k;
}

__host__ __device__ constexpr K7 make_even(const K7& a){
    K7 k{};
    for(int i=0;i<7;i++) for(int j=0;j<7;j++) k.w[i][j] = (a.w[i][j] + a.w[i][6-j]) * 0.5f;
    return k;
}
__host__ __device__ constexpr K7 make_odd(const K7& a){
    K7 k{};
    for(int i=0;i<7;i++) for(int j=0;j<7;j++) k.w[i][j] = (a.w[i][j] - a.w[i][6-j]) * 0.5f;
    return k;
}

__device__ constexpr double RS2 = 0.70710678118654752440;
__device__ constexpr K7 KL3   = make_log(1, 0.8);
__device__ constexpr K7 KL5   = make_log(2, 1.0);
__device__ constexpr K7 KL7   = make_log(3, 1.4);
__device__ constexpr K7 KG0   = make_gabor( 1.0, 0.0);
__device__ constexpr K7 KG45  = make_gabor( RS2, RS2);
__device__ constexpr K7 KG90  = make_gabor( 0.0, 1.0);
__device__ constexpr K7 KGE   = make_even(KG45);
__device__ constexpr K7 KGO   = make_odd(KG45);
__device__ constexpr K7 KLP   = make_lpf();
__device__ constexpr K7 KH3   = make_hpf3();
__device__ constexpr K7 KH5   = make_hpf5();

// ---------------------------------------------------------------------------
#define IMG_SZ 262144        // 512*512
#define PLANE  12582912      // 48*512*512
#define PITCH  72
#define BROWS  64            // circular buffer rows (&63)

__device__ __forceinline__ float addi(float a, float b){
    float d; asm("fma.rn.f32 %0, %1, 0f3F800000, %2;" : "=f"(d) : "f"(a), "f"(b)); return d;
}
__device__ __forceinline__ float subi(float a, float b){   // a - b
    float d; asm("fma.rn.f32 %0, %1, 0fBF800000, %2;" : "=f"(d) : "f"(b), "f"(a)); return d;
}

__device__ __forceinline__ float htanh(float z){     // tanh(z) via MUFU.TANH
    float t;
    asm("tanh.approx.f32 %0, %1;" : "=f"(t) : "f"(z));
    return t;
}

__device__ __forceinline__ void cpasync4(unsigned int daddr, const float* src, unsigned int sz){
    asm volatile("cp.async.ca.shared.global [%0], [%1], 4, %2;"
                 :: "r"(daddr), "l"(src), "r"(sz) : "memory");
}

// streaming (evict-first) 128-bit store: outputs are write-once, never re-read
__device__ __forceinline__ void stcs4(float* p, float4 v){
    asm volatile("st.global.cs.v4.f32 [%0], {%1, %2, %3, %4};"
                 :: "l"(p), "f"(v.x), "f"(v.y), "f"(v.z), "f"(v.w) : "memory");
}

struct Acc { float l3,l5,l7,h3,h5,lp,g0,g90,gE,gO; };

// Even-symmetric taps for fold-level R. Processed in DESCENDING R order so
// the narrow-filter accumulators (l3/lp/h3 at R<=1, l5/h5 at R<=2) only come
// alive late, minimizing peak register pressure during the wide levels.
template<int R>
__device__ __forceinline__ void taps_even(float vs0, float hs1, float hs2, float hs3, Acc& p){
    p.l7  = fmaf(vs0, KL7.w[3+R][3], p.l7);
    p.l7  = fmaf(hs1, KL7.w[3+R][4], p.l7);
    p.l7  = fmaf(hs2, KL7.w[3+R][5], p.l7);
    p.l7  = fmaf(hs3, KL7.w[3+R][6], p.l7);
    p.g0  = fmaf(vs0, KG0.w[3+R][3], p.g0);
    p.g0  = fmaf(hs1, KG0.w[3+R][4], p.g0);
    p.g0  = fmaf(hs2, KG0.w[3+R][5], p.g0);
    p.g0  = fmaf(hs3, KG0.w[3+R][6], p.g0);
    p.g90 = fmaf(vs0, KG90.w[3+R][3], p.g90);
    p.g90 = fmaf(hs1, KG90.w[3+R][4], p.g90);
    p.g90 = fmaf(hs2, KG90.w[3+R][5], p.g90);
    p.g90 = fmaf(hs3, KG90.w[3+R][6], p.g90);
    p.gE  = fmaf(vs0, KGE.w[3+R][3], p.gE);
    p.gE  = fmaf(hs1, KGE.w[3+R][4], p.gE);
    p.gE  = fmaf(hs2, KGE.w[3+R][5], p.gE);
    p.gE  = fmaf(hs3, KGE.w[3+R][6], p.gE);
    if constexpr (R <= 2){
        p.l5 = fmaf(vs0, KL5.w[3+R][3], p.l5);
        p.l5 = fmaf(hs1, KL5.w[3+R][4], p.l5);
        p.l5 = fmaf(hs2, KL5.w[3+R][5], p.l5);
        p.h5 = fmaf(vs0, KH5.w[3+R][3], p.h5);
        p.h5 = fmaf(hs1, KH5.w[3+R][4], p.h5);
        p.h5 = fmaf(hs2, KH5.w[3+R][5], p.h5);
    }
    if constexpr (R <= 1){
        p.l3 = fmaf(vs0, KL3.w[3+R][3], p.l3);
        p.l3 = fmaf(hs1, KL3.w[3+R][4], p.l3);
        p.lp = fmaf(vs0, KLP.w[3+R][3], p.lp);
        p.lp = fmaf(hs1, KLP.w[3+R][4], p.lp);
        p.h3 = fmaf(vs0, KH3.w[3+R][3], p.h3);
        p.h3 = fmaf(hs1, KH3.w[3+R][4], p.h3);
    }
}

template<int R>
__device__ __forceinline__ void taps_odd(float hd1, float hd2, float hd3, Acc& p){
    p.gO = fmaf(hd1, KGO.w[3+R][4], p.gO);
    p.gO = fmaf(hd2, KGO.w[3+R][5], p.gO);
    p.gO = fmaf(hd3, KGO.w[3+R][6], p.gO);
}

__device__ __forceinline__ void load10(const float* p, float v[10]){
    float4 a = *(const float4*)p;
    float4 b = *(const float4*)(p + 4);
    float2 c = *(const float2*)(p + 8);
    v[0]=a.x; v[1]=a.y; v[2]=a.z; v[3]=a.w;
    v[4]=b.x; v[5]=b.y; v[6]=b.z; v[7]=b.w;
    v[8]=c.x; v[9]=c.y;
}

__device__ __forceinline__ void finalize(const Acc& p, float& lf, float& lo, float& ho, float& go){
    lf = p.lp;
    lo = fmaf(htanh(fmaxf(fmaxf(p.l3, p.l5), p.l7)), 0.5f, 0.5f);
    ho = fmaf(htanh(fmaxf(p.h3, p.h5)), 0.5f, 0.5f);
    go = htanh(fmaxf(fmaxf(p.g0, p.g90), p.gE + fabsf(p.gO)));
}

// Uneven y-strips: blockIdx.y 0,1 -> 176 rows (11 iters), blockIdx.y 2 -> 160
// rows (10 iters). Grid = 8*3*48 = 1152 blocks.
#define STRIP_H 176

__global__ __launch_bounds__(256, 4)
void msfilters_kernel(const float* __restrict__ x, float* __restrict__ out, int planes){
    __shared__ __align__(16) float sm[BROWS * PITCH];

    unsigned int smb;
    asm("{ .reg .u64 t; cvta.to.shared.u64 t, %1; cvt.u32.u64 %0, t; }"
        : "=r"(smb) : "l"((const void*)sm));

    const int img    = blockIdx.z;
    const int x0     = blockIdx.x * 64;
    const int ystart = blockIdx.y * STRIP_H;
    const int iters  = (blockIdx.y == 2) ? 10 : 11;   // 176+176+160 = 512
    const float* src = x + (size_t)img * IMG_SZ;

    // initial fill via cp.async (zero-fill OOB through size-0 trick):
    // logical rows -3..18 -> phys rows 0..21
    for (int idx = threadIdx.x; idx < 22 * 70; idx += 256){
        int r = idx / 70;
        int c = idx - r * 70;
        int gy0 = ystart + r - 3;
        int gx0 = x0 + c - 3;
        bool ok = ((unsigned)gy0 < 512u) && ((unsigned)gx0 < 512u);
        unsigned int d = smb + (unsigned int)((r * PITCH + c) * 4);
        cpasync4(d, src + gy0 * 512 + gx0, ok ? 4u : 0u);
    }
    asm volatile("cp.async.commit_group;" ::: "memory");

    const int tx  = threadIdx.x & 15;
    const int ty  = threadIdx.x >> 4;
    const int tx4 = tx * 4;

    // loop-invariant prefetch state: thread owns row ty, cols tx+16j of the halo
    int gy = ystart + 19 + ty;
    const float* srow = src + (size_t)gy * 512 + (x0 - 3 + tx);
    const int gxb = x0 - 3 + tx;
    const bool v0 = ((unsigned)gxb        < 512u);
    const bool v1 = ((unsigned)(gxb + 16) < 512u);
    const bool v2 = ((unsigned)(gxb + 32) < 512u);
    const bool v3 = ((unsigned)(gxb + 48) < 512u);
    const bool v4 = (tx < 6) && ((unsigned)(gxb + 64) < 512u);

    int ybase   = ty;            // (16k + ty) & 63
    int sts_row = 22 + ty;       // (22 + ty + 16k) & 63

    float* outp = out + (size_t)img * IMG_SZ + (size_t)(ystart + ty) * 512 + x0 + tx4;

    asm volatile("cp.async.wait_group 0;" ::: "memory");
    __syncthreads();

    #pragma unroll 1
    for (int k = 0; k < iters; k++){
        // ---- async prefetch of next 16 rows straight into smem ----
        if (k < iters - 1){
            const bool gok = gy < 512;
            unsigned int d0 = smb + (unsigned int)(((sts_row & 63) * PITCH + tx) * 4);
            cpasync4(d0,       srow,      (v0 && gok) ? 4u : 0u);
            cpasync4(d0 + 64,  srow + 16, (v1 && gok) ? 4u : 0u);
            cpasync4(d0 + 128, srow + 32, (v2 && gok) ? 4u : 0u);
            cpasync4(d0 + 192, srow + 48, (v3 && gok) ? 4u : 0u);
            if (tx < 6)
                cpasync4(d0 + 256, srow + 64, (v4 && gok) ? 4u : 0u);
            asm volatile("cp.async.commit_group;" ::: "memory");
        }

        // ---- compute current 16 output rows from circular smem window ----
        const float* rowp[7];
        #pragma unroll
        for (int d = 0; d < 7; d++)
            rowp[d] = &sm[((ybase + d) & 63) * PITCH + tx4];

        Acc acc[4] = {};

#define LEVEL(R) { \
        float T[10], B[10]; \
        load10(rowp[3-R], T); \
        load10(rowp[3+R], B); \
        float V[10], W[10]; \
        _Pragma("unroll") \
        for (int c = 0; c < 10; c++){ V[c] = addi(T[c], B[c]); W[c] = subi(T[c], B[c]); } \
        _Pragma("unroll") \
        for (int p = 0; p < 4; p++){ \
            const int cc = p + 3; \
            float hs1 = addi(V[cc-1], V[cc+1]); \
            float hs2 = addi(V[cc-2], V[cc+2]); \
            float hs3 = addi(V[cc-3], V[cc+3]); \
            taps_even<R>(V[cc], hs1, hs2, hs3, acc[p]); \
            float hd1 = subi(W[cc-1], W[cc+1]); \
            float hd2 = subi(W[cc-2], W[cc+2]); \
            float hd3 = subi(W[cc-3], W[cc+3]); \
            taps_odd<R>(hd1, hd2, hd3, acc[p]); \
        } }
        // Descending level order: wide filters first (5 accs live), narrow
        // accumulators materialize late -> minimal peak pressure, no spills.
        LEVEL(3)
        LEVEL(2)
        LEVEL(1)
#undef LEVEL

        {   // level 0 (center row) last; also emit the 'original' plane
            float m[10]; load10(rowp[3], m);
            float4 o4; o4.x = m[3]; o4.y = m[4]; o4.z = m[5]; o4.w = m[6];
            stcs4(outp, o4);
            #pragma unroll
            for (int p = 0; p < 4; p++){
                const int cc = p + 3;
                float hs1 = addi(m[cc-1], m[cc+1]);
                float hs2 = addi(m[cc-2], m[cc+2]);
                float hs3 = addi(m[cc-3], m[cc+3]);
                taps_even<0>(m[cc], hs1, hs2, hs3, acc[p]);
            }
        }

        float4 lf4, lo4, ho4, go4;
        finalize(acc[0], lf4.x, lo4.x, ho4.x, go4.x);
        finalize(acc[1], lf4.y, lo4.y, ho4.y, go4.y);
        finalize(acc[2], lf4.z, lo4.z, ho4.z, go4.z);
        finalize(acc[3], lf4.w, lo4.w, ho4.w, go4.w);

        stcs4(outp + (size_t)PLANE,   lf4);
        stcs4(outp + 2*(size_t)PLANE, lo4);
        stcs4(outp + 3*(size_t)PLANE, ho4);
        if (planes >= 5)
            stcs4(outp + 4*(size_t)PLANE, go4);

        // prefetch rows are disjoint (mod 64) from this iteration's read
        // window, so a single barrier per iteration suffices.
        asm volatile("cp.async.wait_group 0;" ::: "memory");
        __syncthreads();

        gy      += 16;
        srow    += 16 * 512;
        outp    += 16 * 512;
        ybase   += 16;
        sts_row += 16;
    }
}

extern "C" void kernel_launch(void* const* d_in, const int* in_sizes, int n_in,
                              void* d_out, int out_size){
    const float* x = (const float*)d_in[0];
    float* out = (float*)d_out;
    const int planes = out_size / PLANE;   // 5 when use_gabor
    dim3 grid(8, 3, 48);
    dim3 block(256);
    msfilters_kernel<<<grid, block>>>(x, out, planes);
}